// round 17
// baseline (speedup 1.0000x reference)
#include <cuda_runtime.h>
#include <cuda_bf16.h>
#include <math.h>

#define N_BINS 15
#define NBLK_MAX 1184
#define PCOLS  48
#define GRID_C100 592

__device__ float g_part[NBLK_MAX][PCOLS];
__device__ unsigned int g_ticket;   // zero-init; last block resets each launch

typedef unsigned long long ull;

__device__ __forceinline__ ull addx2(ull a, ull b) {
    ull r; asm("add.rn.f32x2 %0, %1, %2;" : "=l"(r) : "l"(a), "l"(b)); return r;
}
__device__ __forceinline__ ull fmasqx2(ull a, ull c) {  // a*a + c (packed)
    ull r; asm("fma.rn.f32x2 %0, %1, %2, %3;" : "=l"(r) : "l"(a), "l"(a), "l"(c)); return r;
}
__device__ __forceinline__ float2 uf2(ull v) {
    union { ull u; float2 f; } t; t.u = v; return t.f;
}

// C==100: 4 lanes/row, 8 rows/warp-iter, ulonglong2 loads (regs ARE packed
// operands), scalar gather for p[label], fused last-block finalize.
__global__ void __launch_bounds__(256, 4) ece_main_c100(
    const float4* __restrict__ probs4,
    const int* __restrict__ labels,
    float* __restrict__ out,
    int N)
{
    __shared__ float s_cnt[N_BINS], s_cf[N_BINS], s_ac[N_BINS], s_bri;
    const int tid = threadIdx.x;
    if (tid < N_BINS) { s_cnt[tid] = 0.f; s_cf[tid] = 0.f; s_ac[tid] = 0.f; }
    if (tid == 0) s_bri = 0.f;
    __syncthreads();

    const int lane = tid & 31;
    const int k    = lane & 3;           // lane within 4-lane row-group
    const int g    = lane >> 2;          // row-group 0..7
    const int warp = (blockIdx.x * blockDim.x + tid) >> 5;
    const int nwarp = (gridDim.x * blockDim.x) >> 5;
    const int step  = nwarp * 8;

    // run-length bin accumulator (k==0 lanes only)
    int   cur_bin = -1;
    float f_cnt = 0.f, f_cf = 0.f, f_ac = 0.f, briacc = 0.f;

    for (int r8 = warp * 8; r8 < N; r8 += step) {
        int row    = r8 + g;
        bool valid = (row < N);
        int rowc   = valid ? row : 0;

        int lab = labels[rowc];

        const float* rowp = (const float*)(probs4 + (size_t)rowc * 25);
        const ulonglong2* rq = (const ulonglong2*)rowp;

        ulonglong2 q0 = rq[k];
        ulonglong2 q1 = rq[k + 4];
        ulonglong2 q2 = rq[k + 8];
        ulonglong2 q3 = rq[k + 12];
        ulonglong2 q4 = rq[k + 16];
        ulonglong2 q5 = rq[k + 20];
        ulonglong2 q6;
        if (k == 0) q6 = rq[24]; else { q6.x = 0ull; q6.y = 0ull; }

        // p[label] gather (k==0 lanes): line is concurrently in flight -> cheap
        int labc = lab < 0 ? 0 : (lab > 99 ? 99 : lab);
        float pl = 0.f;
        if (k == 0) pl = __ldg(rowp + labc);

        // packed sums / sumsq: regs are already f32x2 pairs
        ull sa = addx2(addx2(q0.x, q0.y), addx2(q1.x, q1.y));
        ull sb = addx2(addx2(q2.x, q2.y), addx2(q3.x, q3.y));
        sa = addx2(sa, addx2(q4.x, q4.y));
        sb = addx2(sb, addx2(q5.x, q5.y));
        sa = addx2(sa, addx2(q6.x, q6.y));

        ull qa = fmasqx2(q0.x, fmasqx2(q0.y, 0ull));
        ull qb = fmasqx2(q1.x, fmasqx2(q1.y, 0ull));
        qa = fmasqx2(q2.x, fmasqx2(q2.y, qa));
        qb = fmasqx2(q3.x, fmasqx2(q3.y, qb));
        qa = fmasqx2(q4.x, fmasqx2(q4.y, qa));
        qb = fmasqx2(q5.x, fmasqx2(q5.y, qb));
        qa = fmasqx2(q6.x, fmasqx2(q6.y, qa));

        // max via float views (union punning: register aliasing, no movs)
        float2 f;
        float m0, m1, m2, m3;
        f = uf2(q0.x); m0 = fmaxf(f.x, f.y);
        f = uf2(q0.y); m1 = fmaxf(f.x, f.y);
        f = uf2(q1.x); m2 = fmaxf(f.x, f.y);
        f = uf2(q1.y); m3 = fmaxf(f.x, f.y);
        f = uf2(q2.x); m0 = fmaxf(m0, fmaxf(f.x, f.y));
        f = uf2(q2.y); m1 = fmaxf(m1, fmaxf(f.x, f.y));
        f = uf2(q3.x); m2 = fmaxf(m2, fmaxf(f.x, f.y));
        f = uf2(q3.y); m3 = fmaxf(m3, fmaxf(f.x, f.y));
        f = uf2(q4.x); m0 = fmaxf(m0, fmaxf(f.x, f.y));
        f = uf2(q4.y); m1 = fmaxf(m1, fmaxf(f.x, f.y));
        f = uf2(q5.x); m2 = fmaxf(m2, fmaxf(f.x, f.y));
        f = uf2(q5.y); m3 = fmaxf(m3, fmaxf(f.x, f.y));
        f = uf2(q6.x); m0 = fmaxf(m0, fmaxf(f.x, f.y));
        f = uf2(q6.y); m1 = fmaxf(m1, fmaxf(f.x, f.y));
        float m = fmaxf(fmaxf(m0, m1), fmaxf(m2, m3));

        // collapse packed -> scalar BEFORE butterfly (3 SHFL/stage not 5)
        float2 fs = uf2(addx2(sa, sb));
        float2 fq = uf2(addx2(qa, qb));
        float s  = fs.x + fs.y;
        float sq = fq.x + fq.y;

        #pragma unroll
        for (int off = 2; off >= 1; off >>= 1) {
            s  += __shfl_xor_sync(0xffffffffu, s,  off);
            sq += __shfl_xor_sync(0xffffffffu, sq, off);
            m   = fmaxf(m, __shfl_xor_sync(0xffffffffu, m, off));
        }

        if (k == 0 && valid) {
            float inv  = __fdividef(1.f, s);
            float conf = m * inv;
            float bri  = sq * inv * inv - 2.f * pl * inv + 1.f;
            float hit  = (pl == m) ? 1.f : 0.f;
            int bin = __float2int_ru(conf * (float)N_BINS) - 1;
            bin = bin < 0 ? 0 : (bin > N_BINS - 1 ? N_BINS - 1 : bin);

            if (bin != cur_bin) {
                if (cur_bin >= 0) {
                    atomicAdd(&s_cnt[cur_bin], f_cnt);
                    atomicAdd(&s_cf[cur_bin],  f_cf);
                    atomicAdd(&s_ac[cur_bin],  f_ac);
                }
                cur_bin = bin; f_cnt = 1.f; f_cf = conf; f_ac = hit;
            } else {
                f_cnt += 1.f; f_cf += conf; f_ac += hit;
            }
            briacc += bri;
        }
    }

    if (cur_bin >= 0) {
        atomicAdd(&s_cnt[cur_bin], f_cnt);
        atomicAdd(&s_cf[cur_bin],  f_cf);
        atomicAdd(&s_ac[cur_bin],  f_ac);
    }
    if (briacc != 0.f) atomicAdd(&s_bri, briacc);
    __syncthreads();

    if (tid < N_BINS) {
        g_part[blockIdx.x][tid]              = s_cnt[tid];
        g_part[blockIdx.x][tid + N_BINS]     = s_cf[tid];
        g_part[blockIdx.x][tid + 2 * N_BINS] = s_ac[tid];
    }
    if (tid == 0) g_part[blockIdx.x][45] = s_bri;

    // fused finalize: last block reduces all partials (L2-hot)
    __shared__ bool is_last;
    __threadfence();
    if (tid == 0) {
        unsigned int tk = atomicAdd(&g_ticket, 1u);
        is_last = (tk == gridDim.x - 1);
    }
    __syncthreads();

    if (is_last) {
        if (tid == 0) g_ticket = 0;
        __shared__ double col[46];
        const int c     = tid & 63;
        const int chunk = tid >> 6;      // 0..3
        if (tid < 46) col[tid] = 0.0;
        __syncthreads();
        if (c < 46) {
            double acc = 0.0;
            for (int b = chunk; b < (int)gridDim.x; b += 4)
                acc += (double)g_part[b][c];
            atomicAdd(&col[c], acc);
        }
        __syncthreads();
        if (tid == 0) {
            double ece = 0.0, mx = 0.0;
            double invN = 1.0 / (double)N;
            #pragma unroll
            for (int b = 0; b < N_BINS; b++) {
                double cc = col[b];
                if (cc > 0.0) {
                    double gap = fabs(col[b + N_BINS] / cc - col[b + 2 * N_BINS] / cc);
                    ece += gap * cc * invN;
                    if (gap > mx) mx = gap;
                }
            }
            out[0] = (float)ece;
            out[1] = (float)mx;
            out[2] = (float)(col[45] * invN);
        }
    }
}

// Generic fallback: warp-per-row, fused finalize.
__global__ void ece_main_generic(const float* __restrict__ probs,
                                 const int* __restrict__ labels,
                                 float* __restrict__ out,
                                 int N, int C) {
    __shared__ float s_cnt[N_BINS], s_cf[N_BINS], s_ac[N_BINS], s_bri;
    if (threadIdx.x < N_BINS) {
        s_cnt[threadIdx.x] = 0.f; s_cf[threadIdx.x] = 0.f; s_ac[threadIdx.x] = 0.f;
    }
    if (threadIdx.x == 0) s_bri = 0.f;
    __syncthreads();

    const int lane  = threadIdx.x & 31;
    const int warp  = (blockIdx.x * blockDim.x + threadIdx.x) >> 5;
    const int nwarp = (gridDim.x * blockDim.x) >> 5;

    float acc_count = 0.f, acc_conf = 0.f, acc_acc = 0.f, acc_bri = 0.f;

    for (int row = warp; row < N; row += nwarp) {
        const float* rp = probs + (size_t)row * C;
        float s = 0.f, sq = 0.f, m = -1.f;
        for (int c = lane; c < C; c += 32) {
            float x = rp[c];
            s += x; sq += x * x;
            m = fmaxf(m, x);
        }
        #pragma unroll
        for (int off = 16; off >= 1; off >>= 1) {
            s  += __shfl_xor_sync(0xffffffffu, s,  off);
            sq += __shfl_xor_sync(0xffffffffu, sq, off);
            m = fmaxf(m, __shfl_xor_sync(0xffffffffu, m, off));
        }
        int lab = labels[row];
        int labc = lab < 0 ? 0 : (lab >= C ? C - 1 : lab);
        float pl = rp[labc];
        float inv  = __fdividef(1.f, s);
        float conf = m * inv;
        float bri  = sq * inv * inv - 2.f * pl * inv + 1.f;
        float hit  = (pl == m) ? 1.f : 0.f;
        int bin = __float2int_ru(conf * (float)N_BINS) - 1;
        bin = bin < 0 ? 0 : (bin > N_BINS - 1 ? N_BINS - 1 : bin);
        if (lane == bin) { acc_count += 1.f; acc_conf += conf; acc_acc += hit; }
        if (lane == 0) acc_bri += bri;
    }

    if (lane < N_BINS && acc_count > 0.f) {
        atomicAdd(&s_cnt[lane], acc_count);
        atomicAdd(&s_cf[lane],  acc_conf);
        atomicAdd(&s_ac[lane],  acc_acc);
    }
    if (lane == 0 && acc_bri != 0.f) atomicAdd(&s_bri, acc_bri);
    __syncthreads();

    {
        int t = threadIdx.x;
        if (t < N_BINS) {
            g_part[blockIdx.x][t]              = s_cnt[t];
            g_part[blockIdx.x][t + N_BINS]     = s_cf[t];
            g_part[blockIdx.x][t + 2 * N_BINS] = s_ac[t];
        }
        if (t == 0) g_part[blockIdx.x][45] = s_bri;
    }

    __shared__ bool is_last;
    __threadfence();
    if (threadIdx.x == 0) {
        unsigned int tk = atomicAdd(&g_ticket, 1u);
        is_last = (tk == gridDim.x - 1);
    }
    __syncthreads();

    if (is_last) {
        if (threadIdx.x == 0) g_ticket = 0;
        __shared__ double col[46];
        const int c     = threadIdx.x & 63;
        const int chunk = threadIdx.x >> 6;
        if (threadIdx.x < 46) col[threadIdx.x] = 0.0;
        __syncthreads();
        if (c < 46) {
            double acc = 0.0;
            for (int b = chunk; b < (int)gridDim.x; b += 4)
                acc += (double)g_part[b][c];
            atomicAdd(&col[c], acc);
        }
        __syncthreads();
        if (threadIdx.x == 0) {
            double ece = 0.0, mx = 0.0;
            double invN = 1.0 / (double)N;
            #pragma unroll
            for (int b = 0; b < N_BINS; b++) {
                double cc = col[b];
                if (cc > 0.0) {
                    double gap = fabs(col[b + N_BINS] / cc - col[b + 2 * N_BINS] / cc);
                    ece += gap * cc * invN;
                    if (gap > mx) mx = gap;
                }
            }
            out[0] = (float)ece;
            out[1] = (float)mx;
            out[2] = (float)(col[45] * invN);
        }
    }
}

extern "C" void kernel_launch(void* const* d_in, const int* in_sizes, int n_in,
                              void* d_out, int out_size) {
    int i_probs = 0, i_labels = 1;
    if (n_in >= 2 && in_sizes[1] > in_sizes[0]) { i_probs = 1; i_labels = 0; }
    const float* probs  = (const float*)d_in[i_probs];
    const int*   labels = (const int*)d_in[i_labels];
    int N = in_sizes[i_labels];
    int C = in_sizes[i_probs] / N;
    float* out = (float*)d_out;

    if (C == 100) {
        ece_main_c100<<<GRID_C100, 256>>>((const float4*)probs, labels, out, N);
    } else {
        ece_main_generic<<<1184, 256>>>(probs, labels, out, N, C);
    }
}